// round 3
// baseline (speedup 1.0000x reference)
#include <cuda_runtime.h>
#include <cuda_bf16.h>
#include <cstdint>

// Problem constants
#define BB 8
#define NN 256
#define DD 128
#define HH 8
#define DH 64
#define DQ 32
#define MAXD 5.0f

// Scratch (device globals; no allocation allowed)
__device__ float g_nproj[BB * NN * DH];   // [B,N,64]
__device__ float g_Weff[DH * DH];         // folded first-layer weight (64x64)
__device__ float g_b1eff[DH];
__device__ float g_w1c[DH];               // W1[:,96] / MAXD

// ---------------------------------------------------------------------------
// Prep 1: fold edge projection into layer-1 weights.
//   Weff[o][k] = W1[o][k] + sum_m W1[o][64+m] * W_edge[m][k]   (k < 64)
//   b1eff[o]   = b1[o]    + sum_m W1[o][64+m] * b_edge[m]
//   w1c[o]     = W1[o][96] / MAXD
// ---------------------------------------------------------------------------
__global__ void prep_weights_kernel(const float* __restrict__ W_edge,
                                    const float* __restrict__ b_edge,
                                    const float* __restrict__ W1,
                                    const float* __restrict__ b1) {
    int t = threadIdx.x;  // 256 threads, 1 block
    for (int idx = t; idx < DH * DH; idx += 256) {
        int o = idx >> 6, k = idx & 63;
        float acc = W1[o * 97 + k];
        #pragma unroll
        for (int m = 0; m < DQ; ++m)
            acc = fmaf(W1[o * 97 + 64 + m], W_edge[m * DD + k], acc);
        g_Weff[idx] = acc;
    }
    if (t < DH) {
        float acc = b1[t];
        #pragma unroll
        for (int m = 0; m < DQ; ++m)
            acc = fmaf(W1[t * 97 + 64 + m], b_edge[m], acc);
        g_b1eff[t] = acc;
        g_w1c[t] = W1[t * 97 + 96] * (1.0f / MAXD);
    }
}

// ---------------------------------------------------------------------------
// Prep 2: nproj[b][i][o] = node_features[b][i] . W_node[o] + b_node[o]
// ---------------------------------------------------------------------------
__global__ void prep_nproj_kernel(const float* __restrict__ nf,
                                  const float* __restrict__ Wn,
                                  const float* __restrict__ bn) {
    int row = blockIdx.x;            // b*N + i  (2048 blocks)
    int o = threadIdx.x;             // 64 threads
    __shared__ float sx[DD];
    const float* x = nf + (size_t)row * DD;
    sx[o] = x[o];
    sx[o + 64] = x[o + 64];
    __syncthreads();
    const float* w = Wn + o * DD;
    float a0 = 0.f, a1 = 0.f, a2 = 0.f, a3 = 0.f;
    #pragma unroll
    for (int k = 0; k < DD; k += 4) {
        a0 = fmaf(w[k + 0], sx[k + 0], a0);
        a1 = fmaf(w[k + 1], sx[k + 1], a1);
        a2 = fmaf(w[k + 2], sx[k + 2], a2);
        a3 = fmaf(w[k + 3], sx[k + 3], a3);
    }
    g_nproj[row * DH + o] = (a0 + a1) + (a2 + a3) + bn[o];
}

// ---------------------------------------------------------------------------
// Main: one CTA per (b, i); thread j handles edge (i, j).
//   ef  = tanh(nproj_i + nproj_j)           (64, regs)
//   h1o = relu(Weff[o].ef + cd*w1c[o] + b1eff[o])   streamed
//   h2  += W2t[o][:] * h1o                  (32 accumulators, regs)
//   p   = sigmoid(W3.relu(h2) + b3), masked, written transposed [B,H,N,N]
// ---------------------------------------------------------------------------
#define NP_PITCH 65  // odd pitch -> conflict-free per-row smem reads

__global__ __launch_bounds__(256)
void sparsity_main_kernel(const float* __restrict__ chem,
                          const int* __restrict__ mask,
                          const float* __restrict__ W2,
                          const float* __restrict__ b2,
                          const float* __restrict__ W3,
                          const float* __restrict__ b3,
                          float* __restrict__ out) {
    const int i = blockIdx.x;
    const int b = blockIdx.y;
    const int tid = threadIdx.x;  // == j

    extern __shared__ float sm[];
    float* s_np  = sm;                       // 256*65
    float* s_W   = s_np + NN * NP_PITCH;     // 4096  (Weff, row-major 64x64)
    float* s_W2t = s_W + DH * DH;            // 2048  (W2 transposed: [o][m])
    float* s_W3t = s_W2t + DH * DQ;          // 256   (W3 transposed: [m][h])
    float* s_b1  = s_W3t + DQ * HH;          // 64
    float* s_w1c = s_b1 + DH;                // 64
    float* s_b2  = s_w1c + DH;               // 32
    float* s_b3  = s_b2 + DQ;                // 8

    // --- cooperative smem fill ---
    const float4* np_b4 = reinterpret_cast<const float4*>(g_nproj + (size_t)b * NN * DH);
    for (int idx4 = tid; idx4 < NN * DH / 4; idx4 += 256) {
        int r = idx4 >> 4;          // row (j)
        int c = (idx4 & 15) * 4;    // col
        float4 v = np_b4[idx4];
        float* d = s_np + r * NP_PITCH + c;
        d[0] = v.x; d[1] = v.y; d[2] = v.z; d[3] = v.w;
    }
    for (int idx = tid; idx < DH * DH; idx += 256) s_W[idx] = g_Weff[idx];
    for (int idx = tid; idx < DQ * DH; idx += 256) {
        int m = idx >> 6, o = idx & 63;
        s_W2t[o * DQ + m] = W2[idx];
    }
    if (tid < HH * DQ) {
        int h = tid >> 5, m = tid & 31;
        s_W3t[m * HH + h] = W3[tid];
    }
    if (tid < DH) { s_b1[tid] = g_b1eff[tid]; s_w1c[tid] = g_w1c[tid]; }
    if (tid < DQ) s_b2[tid] = b2[tid];
    if (tid < HH) s_b3[tid] = b3[tid];
    __syncthreads();

    const int j = tid;
    const float* ni = s_np + i * NP_PITCH;
    const float* nj = s_np + j * NP_PITCH;

    // ef in registers
    float ef[DH];
    #pragma unroll
    for (int k = 0; k < DH; ++k) {
        float v = ni[k] + nj[k];
        asm("tanh.approx.f32 %0, %0;" : "+f"(v));
        ef[k] = v;
    }

    float cd = chem[((size_t)b * NN + i) * NN + j];
    cd = fminf(fmaxf(cd, 0.0f), MAXD);

    float h2a[DQ];
    #pragma unroll
    for (int m = 0; m < DQ; ++m) h2a[m] = s_b2[m];

    // streamed layer 1 -> layer 2
    #pragma unroll 2
    for (int o = 0; o < DH; ++o) {
        const float* w = s_W + o * DH;
        float a0 = 0.f, a1 = 0.f, a2 = 0.f, a3 = 0.f;
        #pragma unroll
        for (int k = 0; k < DH; k += 4) {
            a0 = fmaf(w[k + 0], ef[k + 0], a0);
            a1 = fmaf(w[k + 1], ef[k + 1], a1);
            a2 = fmaf(w[k + 2], ef[k + 2], a2);
            a3 = fmaf(w[k + 3], ef[k + 3], a3);
        }
        float h1 = (a0 + a1) + (a2 + a3) + s_b1[o] + cd * s_w1c[o];
        h1 = fmaxf(h1, 0.0f);
        const float* w2 = s_W2t + o * DQ;
        #pragma unroll
        for (int m = 0; m < DQ; ++m) h2a[m] = fmaf(w2[m], h1, h2a[m]);
    }

    #pragma unroll
    for (int m = 0; m < DQ; ++m) h2a[m] = fmaxf(h2a[m], 0.0f);

    const float msk = (mask[b * NN + i] && mask[b * NN + j]) ? 1.0f : 0.0f;
    float* ob = out + (size_t)b * HH * NN * NN + (size_t)i * NN + j;

    #pragma unroll
    for (int h = 0; h < HH; ++h) {
        float acc = s_b3[h];
        #pragma unroll
        for (int m = 0; m < DQ; ++m) acc = fmaf(s_W3t[m * HH + h], h2a[m], acc);
        float p = 1.0f / (1.0f + __expf(-acc));
        ob[(size_t)h * NN * NN] = p * msk;
    }
}

// ---------------------------------------------------------------------------
// Launch
// ---------------------------------------------------------------------------
extern "C" void kernel_launch(void* const* d_in, const int* in_sizes, int n_in,
                              void* d_out, int out_size) {
    const float* nf     = (const float*)d_in[0];   // node_features
    const float* chem   = (const float*)d_in[1];   // chemical_distances
    const int*   mask   = (const int*)d_in[2];     // node_mask (bool stored as int32)
    const float* W_node = (const float*)d_in[3];
    const float* b_node = (const float*)d_in[4];
    const float* W_edge = (const float*)d_in[5];
    const float* b_edge = (const float*)d_in[6];
    const float* W1     = (const float*)d_in[7];
    const float* b1     = (const float*)d_in[8];
    const float* W2     = (const float*)d_in[9];
    const float* b2     = (const float*)d_in[10];
    const float* W3     = (const float*)d_in[11];
    const float* b3     = (const float*)d_in[12];
    float* out = (float*)d_out;

    const int smem_bytes = (NN * NP_PITCH + DH * DH + DQ * DH + DQ * HH
                            + DH + DH + DQ + HH) * (int)sizeof(float);
    cudaFuncSetAttribute(sparsity_main_kernel,
                         cudaFuncAttributeMaxDynamicSharedMemorySize, smem_bytes);

    prep_weights_kernel<<<1, 256>>>(W_edge, b_edge, W1, b1);
    prep_nproj_kernel<<<BB * NN, DH>>>(nf, W_node, b_node);

    dim3 grid(NN, BB);
    sparsity_main_kernel<<<grid, 256, smem_bytes>>>(chem, mask, W2, b2, W3, b3, out);
}

// round 6
// speedup vs baseline: 2.3223x; 2.3223x over previous
#include <cuda_runtime.h>
#include <cuda_bf16.h>
#include <cstdint>

#define BB 8
#define NN 256
#define DD 128
#define HH 8
#define DH 64
#define DQ 32
#define MAXD 5.0f

// ---------------- device scratch (no allocation allowed) ----------------
__device__ float         g_nproj[BB * NN * DH];   // [B,N,64] fp32
__device__ __nv_bfloat16 g_Wb1[DH * DH];          // folded layer-1 weight [o][k] bf16
__device__ __nv_bfloat16 g_Wb2[DQ * DH];          // W2 [m][o] bf16
__device__ float         g_b1eff[DH];
__device__ float         g_w1c[DH];               // W1[:,96]/MAXD

// ---------------- helpers ----------------
__device__ __forceinline__ uint32_t smem_u32(const void* p) {
    uint32_t a;
    asm("{ .reg .u64 t; cvta.to.shared.u64 t, %1; cvt.u32.u64 %0, t; }" : "=r"(a) : "l"(p));
    return a;
}
#define SWZ128(off) ((off) ^ (((off) >> 3) & 0x70))

// pack -> bf16x2 {lo=a, hi=b}
#define PACK_BF16X2(res, a, b) \
    asm("cvt.rn.satfinite.bf16x2.f32 %0, %1, %2;" : "=r"(res) : "f"(b), "f"(a))

#define STS128(a, r0, r1, r2, r3) \
    asm volatile("st.shared.v4.b32 [%0], {%1,%2,%3,%4};" :: "r"(a), "r"(r0), "r"(r1), "r"(r2), "r"(r3) : "memory")

__device__ __forceinline__ void ldsm_x4(uint32_t* r, uint32_t addr) {
    asm volatile("ldmatrix.sync.aligned.m8n8.x4.shared.b16 {%0,%1,%2,%3}, [%4];"
                 : "=r"(r[0]), "=r"(r[1]), "=r"(r[2]), "=r"(r[3]) : "r"(addr));
}
__device__ __forceinline__ void ldsm_x2(uint32_t* r, uint32_t addr) {
    asm volatile("ldmatrix.sync.aligned.m8n8.x2.shared.b16 {%0,%1}, [%2];"
                 : "=r"(r[0]), "=r"(r[1]) : "r"(addr));
}
__device__ __forceinline__ void mma16816(float& d0, float& d1, float& d2, float& d3,
                                         uint32_t a0, uint32_t a1, uint32_t a2, uint32_t a3,
                                         uint32_t b0, uint32_t b1) {
    asm volatile("mma.sync.aligned.m16n8k16.row.col.f32.bf16.bf16.f32 "
                 "{%0,%1,%2,%3}, {%4,%5,%6,%7}, {%8,%9}, {%0,%1,%2,%3};"
                 : "+f"(d0), "+f"(d1), "+f"(d2), "+f"(d3)
                 : "r"(a0), "r"(a1), "r"(a2), "r"(a3), "r"(b0), "r"(b1));
}

// ---------------- SMEM layout (dynamic) ----------------
#define SM_BUF   0        // 256 rows x 128B : ef -> h1 -> h2      (32768)
#define SM_WB1   32768    // 64 x 128B swizzled                    (8192)
#define SM_WB2   40960    // 32 x 128B swizzled                    (4096)
#define SM_CD    45056    // 256 f                                 (1024)
#define SM_NI    46080    // 64 f
#define SM_B1    46336    // 64 f
#define SM_W1C   46592    // 64 f
#define SM_B2    46848    // 32 f
#define SM_B3    46976    // 8 f
#define SM_W3    47008    // 256 f
#define SM_TOTAL 48032

// ---------------------------------------------------------------------------
// prep: fold edge-proj into W1, emit bf16 weights. grid 96 x 64 threads.
// ---------------------------------------------------------------------------
__global__ void prep_weights_kernel(const float* __restrict__ W_edge,
                                    const float* __restrict__ b_edge,
                                    const float* __restrict__ W1,
                                    const float* __restrict__ b1,
                                    const float* __restrict__ W2) {
    int blk = blockIdx.x, k = threadIdx.x;
    if (blk < DH) {
        int o = blk;
        float acc = W1[o * 97 + k];
        #pragma unroll
        for (int m = 0; m < DQ; ++m)
            acc = fmaf(W1[o * 97 + 64 + m], W_edge[m * DD + k], acc);
        g_Wb1[o * DH + k] = __float2bfloat16_rn(acc);
        if (k == 0) {
            float bb = b1[o];
            #pragma unroll
            for (int m = 0; m < DQ; ++m)
                bb = fmaf(W1[o * 97 + 64 + m], b_edge[m], bb);
            g_b1eff[o] = bb;
            g_w1c[o] = W1[o * 97 + 96] * (1.0f / MAXD);
        }
    } else {
        int m = blk - DH;   // 0..31
        g_Wb2[m * DH + k] = __float2bfloat16_rn(W2[m * DH + k]);
    }
}

// ---------------------------------------------------------------------------
// prep: nproj[b][i][o] = node_features[b][i] . W_node[o] + b_node[o]
// ---------------------------------------------------------------------------
__global__ void prep_nproj_kernel(const float* __restrict__ nf,
                                  const float* __restrict__ Wn,
                                  const float* __restrict__ bn) {
    int row = blockIdx.x;
    int o = threadIdx.x;
    __shared__ float sx[DD];
    const float* x = nf + (size_t)row * DD;
    sx[o] = x[o];
    sx[o + 64] = x[o + 64];
    __syncthreads();
    const float* w = Wn + o * DD;
    float a0 = 0.f, a1 = 0.f, a2 = 0.f, a3 = 0.f;
    #pragma unroll
    for (int k = 0; k < DD; k += 4) {
        a0 = fmaf(w[k + 0], sx[k + 0], a0);
        a1 = fmaf(w[k + 1], sx[k + 1], a1);
        a2 = fmaf(w[k + 2], sx[k + 2], a2);
        a3 = fmaf(w[k + 3], sx[k + 3], a3);
    }
    g_nproj[row * DH + o] = (a0 + a1) + (a2 + a3) + bn[o];
}

// ---------------------------------------------------------------------------
// Main: CTA per (b,i). Warp-level mma.sync bf16 for layers 1-2.
// ---------------------------------------------------------------------------
__global__ __launch_bounds__(256, 2)
void sparsity_main_kernel(const float* __restrict__ chem,
                          const int* __restrict__ mask,
                          const float* __restrict__ b2,
                          const float* __restrict__ W3,
                          const float* __restrict__ b3,
                          float* __restrict__ out) {
    const int i = blockIdx.x;
    const int b = blockIdx.y;
    const int tid = threadIdx.x;            // == row j
    const int lane = tid & 31;
    const int wid = tid >> 5;

    extern __shared__ char sm[];
    const uint32_t smb = smem_u32(sm);
    float* smf = (float*)sm;

    // ---- cooperative smem fills ----
    for (int idx = tid; idx < DH * DH; idx += 256) {       // Wb1 swizzled [o][k]
        int r = idx >> 6, c = idx & 63;
        *(__nv_bfloat16*)(sm + SM_WB1 + SWZ128((uint32_t)(r * 128 + c * 2))) = g_Wb1[idx];
    }
    for (int idx = tid; idx < DQ * DH; idx += 256) {       // Wb2 swizzled [m][o]
        int r = idx >> 6, c = idx & 63;
        *(__nv_bfloat16*)(sm + SM_WB2 + SWZ128((uint32_t)(r * 128 + c * 2))) = g_Wb2[idx];
    }
    if (tid < DH) {
        smf[SM_NI / 4 + tid]  = g_nproj[((size_t)b * NN + i) * DH + tid];
        smf[SM_B1 / 4 + tid]  = g_b1eff[tid];
        smf[SM_W1C / 4 + tid] = g_w1c[tid];
    }
    if (tid < DQ) smf[SM_B2 / 4 + tid] = b2[tid];
    if (tid < HH) smf[SM_B3 / 4 + tid] = b3[tid];
    smf[SM_W3 / 4 + tid] = W3[tid];

    // per-thread row data
    float npj[DH];
    {
        const float4* rp = (const float4*)(g_nproj + ((size_t)b * NN + tid) * DH);
        #pragma unroll
        for (int q = 0; q < 16; ++q) {
            float4 v = rp[q];
            npj[4*q] = v.x; npj[4*q+1] = v.y; npj[4*q+2] = v.z; npj[4*q+3] = v.w;
        }
    }
    float cd = chem[((size_t)b * NN + i) * NN + tid];
    cd = fminf(fmaxf(cd, 0.0f), MAXD);
    smf[SM_CD / 4 + tid] = cd;
    const float msk = (mask[b * NN + i] && mask[b * NN + tid]) ? 1.0f : 0.0f;

    __syncthreads();   // s_ni ready

    // ---- ef = tanh(nproj_i + nproj_j) -> bf16 -> swizzled BUF ----
    {
        const float* s_ni = smf + SM_NI / 4;
        uint32_t efp[DH / 2];
        #pragma unroll
        for (int p = 0; p < DH / 2; ++p) {
            float e0 = npj[2*p]     + s_ni[2*p];
            float e1 = npj[2*p + 1] + s_ni[2*p + 1];
            asm("tanh.approx.f32 %0, %0;" : "+f"(e0));
            asm("tanh.approx.f32 %0, %0;" : "+f"(e1));
            PACK_BF16X2(efp[p], e0, e1);
        }
        #pragma unroll
        for (int c = 0; c < 8; ++c) {
            uint32_t off = SWZ128((uint32_t)(tid * 128 + c * 16));
            STS128(smb + SM_BUF + off, efp[4*c], efp[4*c+1], efp[4*c+2], efp[4*c+3]);
        }
    }
    __syncthreads();   // ef + weights visible

    // ================= warp-local tensor pipeline =================
    const int m_base = wid * 32;
    const int g   = lane >> 2;
    const int tig = lane & 3;
    const int rA  = m_base + (lane & 15);          // A-frag row for this lane
    const int chA = (lane >> 4);                   // +8-col chunk select
    const int rB  = (lane & 7);                    // B-frag row-in-tile
    const int chB = (lane >> 3) & 1;

    // ---- layer 1: A-frags from ef ----
    uint32_t a1f[2][4][4];
    #pragma unroll
    for (int mt = 0; mt < 2; ++mt)
        #pragma unroll
        for (int kt = 0; kt < 4; ++kt)
            ldsm_x4(a1f[mt][kt],
                    smb + SM_BUF + SWZ128((uint32_t)((rA + mt * 16) * 128 + (2*kt + chA) * 16)));
    __syncwarp();

    float cdA[2][2];
    #pragma unroll
    for (int mt = 0; mt < 2; ++mt) {
        cdA[mt][0] = smf[SM_CD / 4 + m_base + mt * 16 + g];
        cdA[mt][1] = smf[SM_CD / 4 + m_base + mt * 16 + g + 8];
    }

    #pragma unroll
    for (int nb = 0; nb < 8; ++nb) {
        uint32_t bf[4][2];
        #pragma unroll
        for (int kt = 0; kt < 4; ++kt)
            ldsm_x2(bf[kt],
                    smb + SM_WB1 + SWZ128((uint32_t)((nb * 8 + rB) * 128 + (2*kt + chB) * 16)));
        const int c0 = nb * 8 + 2 * tig;
        const float b1a = smf[SM_B1 / 4 + c0],     b1b = smf[SM_B1 / 4 + c0 + 1];
        const float wca = smf[SM_W1C / 4 + c0],    wcb = smf[SM_W1C / 4 + c0 + 1];
        #pragma unroll
        for (int mt = 0; mt < 2; ++mt) {
            float d0 = 0.f, d1 = 0.f, d2 = 0.f, d3 = 0.f;
            #pragma unroll
            for (int kt = 0; kt < 4; ++kt)
                mma16816(d0, d1, d2, d3,
                         a1f[mt][kt][0], a1f[mt][kt][1], a1f[mt][kt][2], a1f[mt][kt][3],
                         bf[kt][0], bf[kt][1]);
            float v00 = fmaxf(d0 + b1a + cdA[mt][0] * wca, 0.f);
            float v01 = fmaxf(d1 + b1b + cdA[mt][0] * wcb, 0.f);
            float v10 = fmaxf(d2 + b1a + cdA[mt][1] * wca, 0.f);
            float v11 = fmaxf(d3 + b1b + cdA[mt][1] * wcb, 0.f);
            uint32_t p0, p1;
            PACK_BF16X2(p0, v00, v01);
            PACK_BF16X2(p1, v10, v11);
            const int row0 = m_base + mt * 16 + g;
            asm volatile("st.shared.b32 [%0], %1;" ::
                "r"(smb + SM_BUF + SWZ128((uint32_t)(row0 * 128 + c0 * 2))), "r"(p0) : "memory");
            asm volatile("st.shared.b32 [%0], %1;" ::
                "r"(smb + SM_BUF + SWZ128((uint32_t)((row0 + 8) * 128 + c0 * 2))), "r"(p1) : "memory");
        }
    }
    __syncwarp();

    // ---- layer 2: A-frags from h1 (same BUF) ----
    uint32_t a2f[2][4][4];
    #pragma unroll
    for (int mt = 0; mt < 2; ++mt)
        #pragma unroll
        for (int kt = 0; kt < 4; ++kt)
            ldsm_x4(a2f[mt][kt],
                    smb + SM_BUF + SWZ128((uint32_t)((rA + mt * 16) * 128 + (2*kt + chA) * 16)));
    __syncwarp();

    #pragma unroll
    for (int nb = 0; nb < 4; ++nb) {
        uint32_t bf[4][2];
        #pragma unroll
        for (int kt = 0; kt < 4; ++kt)
            ldsm_x2(bf[kt],
                    smb + SM_WB2 + SWZ128((uint32_t)((nb * 8 + rB) * 128 + (2*kt + chB) * 16)));
        const int c0 = nb * 8 + 2 * tig;
        const float b2a = smf[SM_B2 / 4 + c0], b2b = smf[SM_B2 / 4 + c0 + 1];
        #pragma unroll
        for (int mt = 0; mt < 2; ++mt) {
            float d0 = 0.f, d1 = 0.f, d2 = 0.f, d3 = 0.f;
            #pragma unroll
            for (int kt = 0; kt < 4; ++kt)
                mma16816(d0, d1, d2, d3,
                         a2f[mt][kt][0], a2f[mt][kt][1], a2f[mt][kt][2], a2f[mt][kt][3],
                         bf[kt][0], bf[kt][1]);
            const int row0 = m_base + mt * 16 + g;
            const int row1 = row0 + 8;
            // h2 fp32, bank-rotated within each 128B row (overwrites h1; h1 already in regs)
            *(float*)(sm + SM_BUF + row0 * 128 + (((c0    ) + row0) & 31) * 4) = fmaxf(d0 + b2a, 0.f);
            *(float*)(sm + SM_BUF + row0 * 128 + (((c0 + 1) + row0) & 31) * 4) = fmaxf(d1 + b2b, 0.f);
            *(float*)(sm + SM_BUF + row1 * 128 + (((c0    ) + row1) & 31) * 4) = fmaxf(d2 + b2a, 0.f);
            *(float*)(sm + SM_BUF + row1 * 128 + (((c0 + 1) + row1) & 31) * 4) = fmaxf(d3 + b2b, 0.f);
        }
    }
    __syncwarp();

    // ---- layer 3 (scalar fp32) + sigmoid + masked coalesced store ----
    {
        float h2[DQ];
        #pragma unroll
        for (int m = 0; m < DQ; ++m)
            h2[m] = *(float*)(sm + SM_BUF + tid * 128 + ((m + tid) & 31) * 4);

        const float* s_W3 = smf + SM_W3 / 4;
        const float* s_b3 = smf + SM_B3 / 4;
        float* ob = out + (size_t)b * HH * NN * NN + (size_t)i * NN + tid;
        #pragma unroll
        for (int h = 0; h < HH; ++h) {
            float acc = s_b3[h];
            #pragma unroll
            for (int m = 0; m < DQ; ++m)
                acc = fmaf(s_W3[h * DQ + m], h2[m], acc);
            float p = 1.0f / (1.0f + __expf(-acc));
            ob[(size_t)h * NN * NN] = p * msk;
        }
    }
}

// ---------------------------------------------------------------------------
extern "C" void kernel_launch(void* const* d_in, const int* in_sizes, int n_in,
                              void* d_out, int out_size) {
    const float* nf     = (const float*)d_in[0];
    const float* chem   = (const float*)d_in[1];
    const int*   mask   = (const int*)d_in[2];     // bool stored as int32
    const float* W_node = (const float*)d_in[3];
    const float* b_node = (const float*)d_in[4];
    const float* W_edge = (const float*)d_in[5];
    const float* b_edge = (const float*)d_in[6];
    const float* W1     = (const float*)d_in[7];
    const float* b1     = (const float*)d_in[8];
    const float* W2     = (const float*)d_in[9];
    const float* b2     = (const float*)d_in[10];
    const float* W3     = (const float*)d_in[11];
    const float* b3     = (const float*)d_in[12];
    float* out = (float*)d_out;

    cudaFuncSetAttribute(sparsity_main_kernel,
                         cudaFuncAttributeMaxDynamicSharedMemorySize, SM_TOTAL);

    prep_weights_kernel<<<DH + DQ, DH>>>(W_edge, b_edge, W1, b1, W2);
    prep_nproj_kernel<<<BB * NN, DH>>>(nf, W_node, b_node);

    dim3 grid(NN, BB);
    sparsity_main_kernel<<<grid, 256, SM_TOTAL>>>(chem, mask, b2, W3, b3, out);
}